// round 6
// baseline (speedup 1.0000x reference)
#include <cuda_runtime.h>
#include <cuda_bf16.h>
#include <cstdint>

// ---------------------------------------------------------------------------
// MultiHeadAttention: warp-mma bf16x3 projections + fused flash attention
//   X:[2,2048,1024]  Wq/Wk/Wv/Wo:[1024,1024]
// ---------------------------------------------------------------------------

#define BATCH   2
#define SEQ     2048
#define DMODEL  1024
#define HEADS   16
#define KDIM    64
#define MTOT    (BATCH * SEQ)           // 4096

// Scratch (device globals; allocation-free).
__device__ float g_Q[MTOT * DMODEL + 256];
__device__ float g_K[MTOT * DMODEL + 256];
__device__ float g_V[MTOT * DMODEL + 256];
__device__ float g_O[MTOT * DMODEL + 256];

// ======================= helpers ===========================================
__device__ __forceinline__ uint32_t smem_u32_of(const void* p) {
    uint32_t a;
    asm("{ .reg .u64 t; cvta.to.shared.u64 t, %1; cvt.u32.u64 %0, t; }"
        : "=r"(a) : "l"(p));
    return a;
}

__device__ __forceinline__ void ldmatrix_x4(uint32_t* r, uint32_t addr) {
    asm volatile("ldmatrix.sync.aligned.m8n8.x4.shared.b16 {%0,%1,%2,%3}, [%4];"
        : "=r"(r[0]), "=r"(r[1]), "=r"(r[2]), "=r"(r[3]) : "r"(addr));
}

__device__ __forceinline__ void mma_bf16(float* c, const uint32_t* a, const uint32_t* b) {
    asm volatile(
        "mma.sync.aligned.m16n8k16.row.col.f32.bf16.bf16.f32 "
        "{%0,%1,%2,%3}, {%4,%5,%6,%7}, {%8,%9}, {%0,%1,%2,%3};"
        : "+f"(c[0]), "+f"(c[1]), "+f"(c[2]), "+f"(c[3])
        : "r"(a[0]), "r"(a[1]), "r"(a[2]), "r"(a[3]), "r"(b[0]), "r"(b[1]));
}

__device__ __forceinline__ void st128(uint32_t addr, uint32_t a, uint32_t b,
                                      uint32_t c, uint32_t d) {
    asm volatile("st.shared.v4.b32 [%0], {%1,%2,%3,%4};"
                 :: "r"(addr), "r"(a), "r"(b), "r"(c), "r"(d) : "memory");
}
__device__ __forceinline__ void sts32(uint32_t addr, uint32_t a) {
    asm volatile("st.shared.u32 [%0], %1;" :: "r"(addr), "r"(a) : "memory");
}

__device__ __forceinline__ float ex2(float x) {
    float r;
    asm("ex2.approx.ftz.f32 %0, %1;" : "=f"(r) : "f"(x));
    return r;
}

// split two floats into packed bf16 hi pair and lo (residual) pair
__device__ __forceinline__ void split2(float x, float y, uint32_t& hi, uint32_t& lo) {
    __nv_bfloat16 hx = __float2bfloat16(x);
    __nv_bfloat16 hy = __float2bfloat16(y);
    __nv_bfloat162 h; h.x = hx; h.y = hy;
    hi = *reinterpret_cast<uint32_t*>(&h);
    __nv_bfloat162 l = __floats2bfloat162_rn(x - __bfloat162float(hx),
                                             y - __bfloat162float(hy));
    lo = *reinterpret_cast<uint32_t*>(&l);
}

// ======================= warp-MMA GEMM (projections) =======================
// C[m,n] = alpha * sum_k A[m,k] * B[n,k]   (B row-major [n,k])
// M-tile 128, N-tile 128, K-chunk 32. 256 threads (8 warps, 4x2).
#define LDSR 40

__global__ __launch_bounds__(256)
void gemm_mma(const float* __restrict__ A, const float* __restrict__ B,
              float* __restrict__ C, int K, int lda, int ldb, int ldc)
{
    __shared__ __align__(16) uint16_t As_hi[128 * LDSR];
    __shared__ __align__(16) uint16_t As_lo[128 * LDSR];
    __shared__ __align__(16) uint16_t Bs_hi[128 * LDSR];
    __shared__ __align__(16) uint16_t Bs_lo[128 * LDSR];

    const int tid  = threadIdx.x;
    const int wid  = tid >> 5;
    const int lane = tid & 31;
    const int m0   = blockIdx.y * 128;
    const int n0   = blockIdx.x * 128;
    const int warp_m = wid & 3;
    const int warp_n = wid >> 2;

    float acc[2][8][4];
    #pragma unroll
    for (int i = 0; i < 2; i++)
        #pragma unroll
        for (int j = 0; j < 8; j++)
            #pragma unroll
            for (int q = 0; q < 4; q++) acc[i][j][q] = 0.f;

    const uint32_t sAhi = smem_u32_of(As_hi), sAlo = smem_u32_of(As_lo);
    const uint32_t sBhi = smem_u32_of(Bs_hi), sBlo = smem_u32_of(Bs_lo);

    const int r    = tid >> 1;
    const int kseg = (tid & 1) * 16;
    const float* pA = A + (long)(m0 + r) * lda + kseg;
    const float* pB = B + (long)(n0 + r) * ldb + kseg;

    float4 va[4], vb[4];
    #pragma unroll
    for (int i = 0; i < 4; i++) {
        va[i] = *reinterpret_cast<const float4*>(pA + i * 4);
        vb[i] = *reinterpret_cast<const float4*>(pB + i * 4);
    }

    for (int k0 = 0; k0 < K; k0 += 32) {
        // ---- split current chunk regs -> SMEM ----
        {
            uint32_t hi[8], lo[8];
            #pragma unroll
            for (int i = 0; i < 4; i++) {
                split2(va[i].x, va[i].y, hi[2 * i],     lo[2 * i]);
                split2(va[i].z, va[i].w, hi[2 * i + 1], lo[2 * i + 1]);
            }
            const uint32_t ad = (uint32_t)(r * LDSR + kseg) * 2;
            st128(sAhi + ad,      hi[0], hi[1], hi[2], hi[3]);
            st128(sAhi + ad + 16, hi[4], hi[5], hi[6], hi[7]);
            st128(sAlo + ad,      lo[0], lo[1], lo[2], lo[3]);
            st128(sAlo + ad + 16, lo[4], lo[5], lo[6], lo[7]);
            #pragma unroll
            for (int i = 0; i < 4; i++) {
                split2(vb[i].x, vb[i].y, hi[2 * i],     lo[2 * i]);
                split2(vb[i].z, vb[i].w, hi[2 * i + 1], lo[2 * i + 1]);
            }
            st128(sBhi + ad,      hi[0], hi[1], hi[2], hi[3]);
            st128(sBhi + ad + 16, hi[4], hi[5], hi[6], hi[7]);
            st128(sBlo + ad,      lo[0], lo[1], lo[2], lo[3]);
            st128(sBlo + ad + 16, lo[4], lo[5], lo[6], lo[7]);
        }
        __syncthreads();

        // ---- prefetch next chunk (overlaps with MMAs below) ----
        if (k0 + 32 < K) {
            pA += 32; pB += 32;
            #pragma unroll
            for (int i = 0; i < 4; i++) {
                va[i] = *reinterpret_cast<const float4*>(pA + i * 4);
                vb[i] = *reinterpret_cast<const float4*>(pB + i * 4);
            }
        }

        // ---- compute: 2 k-steps of 16 ----
        #pragma unroll
        for (int ks = 0; ks < 32; ks += 16) {
            uint32_t ah[2][4], al[2][4];
            #pragma unroll
            for (int mi = 0; mi < 2; mi++) {
                const int row = warp_m * 32 + mi * 16 + (lane & 15);
                const int col = ks + (lane >> 4) * 8;
                const uint32_t off = (uint32_t)(row * LDSR + col) * 2;
                ldmatrix_x4(ah[mi], sAhi + off);
                ldmatrix_x4(al[mi], sAlo + off);
            }
            #pragma unroll
            for (int ng = 0; ng < 4; ng++) {
                const int nb   = warp_n * 64 + ng * 16;
                const int nrow = nb + (lane & 7) + ((lane >> 4) << 3);
                const int kcol = ks + ((lane >> 3) & 1) * 8;
                const uint32_t off = (uint32_t)(nrow * LDSR + kcol) * 2;
                uint32_t bh[4], bl[4];
                ldmatrix_x4(bh, sBhi + off);
                ldmatrix_x4(bl, sBlo + off);
                #pragma unroll
                for (int mi = 0; mi < 2; mi++) {
                    #pragma unroll
                    for (int nt = 0; nt < 2; nt++) {
                        float* c = acc[mi][ng * 2 + nt];
                        mma_bf16(c, ah[mi], bh + nt * 2);
                        mma_bf16(c, ah[mi], bl + nt * 2);
                        mma_bf16(c, al[mi], bh + nt * 2);
                    }
                }
            }
        }
        __syncthreads();
    }

    // ---- epilogue ----
    const int g  = lane >> 2;
    const int tg = lane & 3;
    #pragma unroll
    for (int mi = 0; mi < 2; mi++) {
        const int row = m0 + warp_m * 32 + mi * 16 + g;
        #pragma unroll
        for (int nt = 0; nt < 8; nt++) {
            const int col = n0 + warp_n * 64 + nt * 8 + tg * 2;
            float2 v0, v1;
            v0.x = acc[mi][nt][0];
            v0.y = acc[mi][nt][1];
            v1.x = acc[mi][nt][2];
            v1.y = acc[mi][nt][3];
            *reinterpret_cast<float2*>(C + (long)row * ldc + col) = v0;
            *reinterpret_cast<float2*>(C + (long)(row + 8) * ldc + col) = v1;
        }
    }
}

// ======================= fused flash attention =============================
// Grid: (SEQ/128, BATCH*HEADS). 256 threads = 8 warps; warp w owns 16 q-rows.
// Q pre-scaled by 0.125*log2(e); softmax in base 2.
#define LDQK 72     // bf16 stride for Q/K tiles (144 B rows)
#define LDVT 136    // bf16 stride for V^T tile (272 B rows)

#define ATT_QH 0
#define ATT_QL 18432
#define ATT_KH 36864
#define ATT_KL 55296
#define ATT_VH 73728
#define ATT_VL 91136
#define ATT_SMEM 108544

__global__ __launch_bounds__(256)
void attn_fused(const float* __restrict__ Q, const float* __restrict__ Kg,
                const float* __restrict__ Vg, float* __restrict__ Og)
{
    extern __shared__ char dsm[];
    const uint32_t sb  = smem_u32_of(dsm);
    const uint32_t sQh = sb + ATT_QH, sQl = sb + ATT_QL;
    const uint32_t sKh = sb + ATT_KH, sKl = sb + ATT_KL;
    const uint32_t sVh = sb + ATT_VH, sVl = sb + ATT_VL;

    const int tid  = threadIdx.x;
    const int wid  = tid >> 5;
    const int lane = tid & 31;
    const int g    = lane >> 2;
    const int tg   = lane & 3;

    const int bh = blockIdx.y;
    const int b  = bh >> 4;
    const int h  = bh & 15;
    const int q0 = blockIdx.x * 128;

    const float* Qp = Q  + ((long)(b * SEQ + q0)) * DMODEL + h * KDIM;
    const float* Kp = Kg + ((long)(b * SEQ)) * DMODEL + h * KDIM;
    const float* Vp = Vg + ((long)(b * SEQ)) * DMODEL + h * KDIM;

    const float SC = 0.125f * 1.4426950408889634f;

    // ---- load Q tile (scaled, hi/lo split) ----
    {
        const int r = tid >> 1, dseg = (tid & 1) * 32;
        const float* gp = Qp + (long)r * DMODEL + dseg;
        uint32_t hi[16], lo[16];
        #pragma unroll
        for (int i = 0; i < 8; i++) {
            float4 v = *reinterpret_cast<const float4*>(gp + i * 4);
            split2(v.x * SC, v.y * SC, hi[2 * i],     lo[2 * i]);
            split2(v.z * SC, v.w * SC, hi[2 * i + 1], lo[2 * i + 1]);
        }
        const uint32_t ad = (uint32_t)(r * LDQK + dseg) * 2;
        #pragma unroll
        for (int q = 0; q < 4; q++) {
            st128(sQh + ad + q * 16, hi[4 * q], hi[4 * q + 1], hi[4 * q + 2], hi[4 * q + 3]);
            st128(sQl + ad + q * 16, lo[4 * q], lo[4 * q + 1], lo[4 * q + 2], lo[4 * q + 3]);
        }
    }
    __syncthreads();

    // ---- extract Q fragments (held in registers for whole kernel) ----
    uint32_t qh[4][4], ql[4][4];
    #pragma unroll
    for (int ks = 0; ks < 4; ks++) {
        const int row = wid * 16 + (lane & 15);
        const int col = ks * 16 + (lane >> 4) * 8;
        const uint32_t off = (uint32_t)(row * LDQK + col) * 2;
        ldmatrix_x4(qh[ks], sQh + off);
        ldmatrix_x4(ql[ks], sQl + off);
    }

    float m_run[2] = {-1e30f, -1e30f};
    float l_run[2] = {0.f, 0.f};
    float acc_o[8][4];
    #pragma unroll
    for (int i = 0; i < 8; i++)
        #pragma unroll
        for (int q = 0; q < 4; q++) acc_o[i][q] = 0.f;

    for (int kv = 0; kv < SEQ; kv += 128) {
        // ---- load K tile [128 s][64 d] hi/lo ----
        {
            const int r = tid >> 1, dseg = (tid & 1) * 32;
            const float* gp = Kp + (long)(kv + r) * DMODEL + dseg;
            uint32_t hi[16], lo[16];
            #pragma unroll
            for (int i = 0; i < 8; i++) {
                float4 v = *reinterpret_cast<const float4*>(gp + i * 4);
                split2(v.x, v.y, hi[2 * i],     lo[2 * i]);
                split2(v.z, v.w, hi[2 * i + 1], lo[2 * i + 1]);
            }
            const uint32_t ad = (uint32_t)(r * LDQK + dseg) * 2;
            #pragma unroll
            for (int q = 0; q < 4; q++) {
                st128(sKh + ad + q * 16, hi[4 * q], hi[4 * q + 1], hi[4 * q + 2], hi[4 * q + 3]);
                st128(sKl + ad + q * 16, lo[4 * q], lo[4 * q + 1], lo[4 * q + 2], lo[4 * q + 3]);
            }
        }
        // ---- load V tile transposed: Vt[d][s], 32B-granule XOR swizzle ----
        {
            const int sp   = tid >> 2;          // s-pair index 0..63
            const int dseg = (tid & 3) * 16;
            const float* g0 = Vp + (long)(kv + 2 * sp) * DMODEL + dseg;
            const float* g1 = g0 + DMODEL;
            float a[16], c[16];
            #pragma unroll
            for (int i = 0; i < 4; i++) {
                *reinterpret_cast<float4*>(&a[4 * i]) = *reinterpret_cast<const float4*>(g0 + 4 * i);
                *reinterpret_cast<float4*>(&c[4 * i]) = *reinterpret_cast<const float4*>(g1 + 4 * i);
            }
            #pragma unroll
            for (int j = 0; j < 16; j++) {
                const int d = dseg + j;
                uint32_t hi, lo;
                split2(a[j], c[j], hi, lo);
                uint32_t off = (uint32_t)(d * LDVT + 2 * sp) * 2;
                off ^= ((uint32_t)(d >> 4) & 3u) << 5;
                sts32(sVh + off, hi);
                sts32(sVl + off, lo);
            }
        }
        __syncthreads();

        // ---- S = Q K^T : per warp 16x128 in 16 n8-tiles ----
        float s_acc[16][4];
        #pragma unroll
        for (int t = 0; t < 16; t++)
            #pragma unroll
            for (int q = 0; q < 4; q++) s_acc[t][q] = 0.f;

        #pragma unroll
        for (int ks = 0; ks < 4; ks++) {
            #pragma unroll
            for (int ng = 0; ng < 8; ng++) {
                const int nrow = ng * 16 + (lane & 7) + ((lane >> 4) << 3);
                const int kcol = ks * 16 + ((lane >> 3) & 1) * 8;
                const uint32_t off = (uint32_t)(nrow * LDQK + kcol) * 2;
                uint32_t bh4[4], bl4[4];
                ldmatrix_x4(bh4, sKh + off);
                ldmatrix_x4(bl4, sKl + off);
                #pragma unroll
                for (int nt = 0; nt < 2; nt++) {
                    float* c = s_acc[ng * 2 + nt];
                    mma_bf16(c, qh[ks], bh4 + nt * 2);
                    mma_bf16(c, qh[ks], bl4 + nt * 2);
                    mma_bf16(c, ql[ks], bh4 + nt * 2);
                }
            }
        }

        // ---- online softmax (base-2) ----
        float mnew0 = m_run[0], mnew1 = m_run[1];
        #pragma unroll
        for (int t = 0; t < 16; t++) {
            mnew0 = fmaxf(mnew0, fmaxf(s_acc[t][0], s_acc[t][1]));
            mnew1 = fmaxf(mnew1, fmaxf(s_acc[t][2], s_acc[t][3]));
        }
        mnew0 = fmaxf(mnew0, __shfl_xor_sync(0xFFFFFFFFu, mnew0, 1));
        mnew0 = fmaxf(mnew0, __shfl_xor_sync(0xFFFFFFFFu, mnew0, 2));
        mnew1 = fmaxf(mnew1, __shfl_xor_sync(0xFFFFFFFFu, mnew1, 1));
        mnew1 = fmaxf(mnew1, __shfl_xor_sync(0xFFFFFFFFu, mnew1, 2));

        const float fac0 = ex2(m_run[0] - mnew0);
        const float fac1 = ex2(m_run[1] - mnew1);
        m_run[0] = mnew0; m_run[1] = mnew1;
        l_run[0] *= fac0; l_run[1] *= fac1;
        #pragma unroll
        for (int i = 0; i < 8; i++) {
            acc_o[i][0] *= fac0; acc_o[i][1] *= fac0;
            acc_o[i][2] *= fac1; acc_o[i][3] *= fac1;
        }

        // ---- P = exp2(S - m); pack into A-fragments (hi/lo) ----
        uint32_t ph[8][4], pl[8][4];
        float rs0 = 0.f, rs1 = 0.f;
        #pragma unroll
        for (int t = 0; t < 16; t++) {
            const float p0 = ex2(s_acc[t][0] - mnew0);
            const float p1 = ex2(s_acc[t][1] - mnew0);
            const float p2 = ex2(s_acc[t][2] - mnew1);
            const float p3 = ex2(s_acc[t][3] - mnew1);
            rs0 += p0 + p1;
            rs1 += p2 + p3;
            const int kk = t >> 1, half = t & 1;
            split2(p0, p1, ph[kk][2 * half],     pl[kk][2 * half]);
            split2(p2, p3, ph[kk][2 * half + 1], pl[kk][2 * half + 1]);
        }
        rs0 += __shfl_xor_sync(0xFFFFFFFFu, rs0, 1);
        rs0 += __shfl_xor_sync(0xFFFFFFFFu, rs0, 2);
        rs1 += __shfl_xor_sync(0xFFFFFFFFu, rs1, 1);
        rs1 += __shfl_xor_sync(0xFFFFFFFFu, rs1, 2);
        l_run[0] += rs0; l_run[1] += rs1;

        // ---- O += P V : k = 128 (8 k-steps), n = 64 (8 n8-tiles) ----
        #pragma unroll
        for (int kk = 0; kk < 8; kk++) {
            #pragma unroll
            for (int ndp = 0; ndp < 4; ndp++) {
                const int nrow = ndp * 16 + (lane & 7) + ((lane >> 4) << 3);
                const int kcol = kk * 16 + ((lane >> 3) & 1) * 8;
                uint32_t off = (uint32_t)(nrow * LDVT + kcol) * 2;
                off ^= ((uint32_t)(nrow >> 4) & 3u) << 5;
                uint32_t vh4[4], vl4[4];
                ldmatrix_x4(vh4, sVh + off);
                ldmatrix_x4(vl4, sVl + off);
                #pragma unroll
                for (int nt = 0; nt < 2; nt++) {
                    float* c = acc_o[ndp * 2 + nt];
                    mma_bf16(c, ph[kk], vh4 + nt * 2);
                    mma_bf16(c, ph[kk], vl4 + nt * 2);
                    mma_bf16(c, pl[kk], vh4 + nt * 2);
                }
            }
        }
        __syncthreads();
    }

    // ---- epilogue: O /= l, write [s][h*64+d] ----
    const float inv0 = 1.0f / l_run[0];
    const float inv1 = 1.0f / l_run[1];
    const long row0 = (long)(b * SEQ + q0 + wid * 16 + g);
    #pragma unroll
    for (int nt = 0; nt < 8; nt++) {
        const int col = h * KDIM + nt * 8 + tg * 2;
        float2 v0, v1;
        v0.x = acc_o[nt][0] * inv0;
        v0.y = acc_o[nt][1] * inv0;
        v1.x = acc_o[nt][2] * inv1;
        v1.y = acc_o[nt][3] * inv1;
        *reinterpret_cast<float2*>(Og + row0 * DMODEL + col) = v0;
        *reinterpret_cast<float2*>(Og + (row0 + 8) * DMODEL + col) = v1;
    }
}

// ---------------------------------------------------------------------------
extern "C" void kernel_launch(void* const* d_in, const int* in_sizes, int n_in,
                              void* d_out, int out_size)
{
    const float* X  = (const float*)d_in[0];
    const float* Wq = (const float*)d_in[1];
    const float* Wk = (const float*)d_in[2];
    const float* Wv = (const float*)d_in[3];
    const float* Wo = (const float*)d_in[4];
    float* out = (float*)d_out;

    float *Q, *K, *V, *O;
    cudaGetSymbolAddress((void**)&Q, g_Q);
    cudaGetSymbolAddress((void**)&K, g_K);
    cudaGetSymbolAddress((void**)&V, g_V);
    cudaGetSymbolAddress((void**)&O, g_O);

    cudaFuncSetAttribute(attn_fused,
                         cudaFuncAttributeMaxDynamicSharedMemorySize, ATT_SMEM);

    const dim3 blk(256);

    // --- 1) Projections ---
    {
        dim3 grid(DMODEL / 128, MTOT / 128);
        gemm_mma<<<grid, blk>>>(X, Wq, Q, DMODEL, DMODEL, DMODEL, DMODEL);
        gemm_mma<<<grid, blk>>>(X, Wk, K, DMODEL, DMODEL, DMODEL, DMODEL);
        gemm_mma<<<grid, blk>>>(X, Wv, V, DMODEL, DMODEL, DMODEL, DMODEL);
    }

    // --- 2) Fused attention ---
    {
        dim3 grid(SEQ / 128, BATCH * HEADS);
        attn_fused<<<grid, blk, ATT_SMEM>>>(Q, K, V, O);
    }

    // --- 3) out = O @ Wo^T ---
    {
        dim3 grid(DMODEL / 128, MTOT / 128);
        gemm_mma<<<grid, blk>>>(O, Wo, out, DMODEL, DMODEL, DMODEL, DMODEL);
    }
}